// round 16
// baseline (speedup 1.0000x reference)
#include <cuda_runtime.h>

#define NSTEP 8192
#define NUDIM 4
#define RB    128
#define NXDIM 64
#define NYDIM 4
#define LBLK  32
#define MBLK  (NSTEP / LBLK)
#define MBLK2 (MBLK / 2)

__device__ float g_F [MBLK * RB * NXDIM];
__device__ float g_F2[MBLK2 * RB * NXDIM];
__device__ float g_Xs[MBLK * RB * NXDIM];
__device__ float g_A32[NXDIM * NXDIM];
__device__ float g_A64[NXDIM * NXDIM];
__device__ float g_G [NXDIM * (LBLK * NUDIM)];

typedef unsigned long long ull;
#define FFMA2(d, a, b)  asm("fma.rn.f32x2 %0, %1, %2, %0;" : "+l"(d) : "l"(a), "l"(b))
#define PACKB(d, s)     asm("mov.b64 %0, {%1, %1};" : "=l"(d) : "f"(s))
#define PACK2(d, lo, hi) asm("mov.b64 %0, {%1, %2};" : "=l"(d) : "f"(lo), "f"(hi))
#define UNPACK2(lo, hi, p) asm("mov.b64 {%0, %1}, %2;" : "=f"(lo), "=f"(hi) : "l"(p))

__device__ __forceinline__ int swz(int row, int r) { return r ^ (((row >> 2) & 7) << 2); }

// ---------------- Kernel 1: A^32, A^64 + G by doubling, 1024 threads ----------------
__global__ void __launch_bounds__(1024) k_powers(const float* __restrict__ A, const float* __restrict__ Bu) {
    extern __shared__ float ps[];
    float* Asm = ps;                 // 64 x 65
    float* P   = ps + NXDIM * 65;    // 64 x 128
    int t = threadIdx.x;

    for (int idx = t; idx < NXDIM * NXDIM; idx += 1024)
        Asm[(idx >> 6) * 65 + (idx & 63)] = A[idx];
    if (t < 256) P[(t >> 2) * 128 + (t & 3)] = Bu[t];
    __syncthreads();

    int W = 4;
    int oi = t >> 4, oj0 = (t & 15) * 4;
    for (int s = 0; s < 5; s++) {
        for (int idx = t; idx < NXDIM * W; idx += 1024) {
            int i = idx / W, k = idx % W;
            float s0 = 0.f, s1 = 0.f, s2 = 0.f, s3 = 0.f;
            #pragma unroll 4
            for (int j = 0; j < NXDIM; j += 4) {
                s0 += Asm[i * 65 + j]     * P[(j)     * 128 + k];
                s1 += Asm[i * 65 + j + 1] * P[(j + 1) * 128 + k];
                s2 += Asm[i * 65 + j + 2] * P[(j + 2) * 128 + k];
                s3 += Asm[i * 65 + j + 3] * P[(j + 3) * 128 + k];
            }
            P[i * 128 + W + k] = (s0 + s1) + (s2 + s3);
        }
        __syncthreads();
        float a0 = 0.f, a1 = 0.f, a2 = 0.f, a3 = 0.f;
        #pragma unroll 8
        for (int k = 0; k < NXDIM; k++) {
            float a = Asm[oi * 65 + k];
            const float* row = Asm + k * 65 + oj0;
            a0 += a * row[0]; a1 += a * row[1]; a2 += a * row[2]; a3 += a * row[3];
        }
        __syncthreads();
        Asm[oi * 65 + oj0]     = a0;
        Asm[oi * 65 + oj0 + 1] = a1;
        Asm[oi * 65 + oj0 + 2] = a2;
        Asm[oi * 65 + oj0 + 3] = a3;
        __syncthreads();
        W <<= 1;
    }

    // Asm = A^32
    for (int idx = t; idx < NXDIM * NXDIM; idx += 1024)
        g_A32[idx] = Asm[(idx >> 6) * 65 + (idx & 63)];
    for (int idx = t; idx < NXDIM * 128; idx += 1024) {
        int i = idx >> 7, col = idx & 127;
        int m = col >> 2, q = col & 3;
        g_G[i * 128 + ((31 - m) << 2) + q] = P[idx];
    }
    __syncthreads();

    // one more squaring -> A^64
    {
        float a0 = 0.f, a1 = 0.f, a2 = 0.f, a3 = 0.f;
        #pragma unroll 8
        for (int k = 0; k < NXDIM; k++) {
            float a = Asm[oi * 65 + k];
            const float* row = Asm + k * 65 + oj0;
            a0 += a * row[0]; a1 += a * row[1]; a2 += a * row[2]; a3 += a * row[3];
        }
        __syncthreads();
        Asm[oi * 65 + oj0]     = a0;
        Asm[oi * 65 + oj0 + 1] = a1;
        Asm[oi * 65 + oj0 + 2] = a2;
        Asm[oi * 65 + oj0 + 3] = a3;
        __syncthreads();
    }
    for (int idx = t; idx < NXDIM * NXDIM; idx += 1024)
        g_A64[idx] = Asm[(idx >> 6) * 65 + (idx & 63)];
}

// ---------------- Kernel 2: f_c = G @ U_c (FFMA2, unchanged) ----------------
__global__ void __launch_bounds__(256) k_fgemm(const float* __restrict__ u) {
    extern __shared__ float sm[];
    float* Gt = sm;
    float* Ut = sm + 128 * NXDIM;
    int t = threadIdx.x, c = blockIdx.x;
    int rb = t & 15, ib = t >> 4;
    int r0 = rb * 8, i0 = ib * 4;
    for (int idx = t; idx < 128 * NXDIM; idx += 256) {
        int i = idx >> 7, k = idx & 127;
        Gt[k * NXDIM + i] = g_G[idx];
    }
    ull pacc[4][4];
    #pragma unroll
    for (int ii = 0; ii < 4; ii++)
        #pragma unroll
        for (int rp = 0; rp < 4; rp++) pacc[ii][rp] = 0ull;
    const float* ublk = u + (size_t)c * (LBLK * NUDIM * RB);
    for (int k0 = 0; k0 < 128; k0 += 32) {
        __syncthreads();
        for (int idx = t; idx < 32 * 128; idx += 256)
            Ut[idx] = ublk[(k0 + (idx >> 7)) * 128 + (idx & 127)];
        __syncthreads();
        #pragma unroll 8
        for (int kk = 0; kk < 32; kk++) {
            float4 g = *(const float4*)(Gt + (k0 + kk) * NXDIM + i0);
            ull g0, g1, g2, g3;
            PACKB(g0, g.x); PACKB(g1, g.y); PACKB(g2, g.z); PACKB(g3, g.w);
            ulonglong2 ua = *(const ulonglong2*)(Ut + kk * 128 + r0);
            ulonglong2 ub = *(const ulonglong2*)(Ut + kk * 128 + r0 + 4);
            ull s0 = ua.x, s1 = ua.y, s2 = ub.x, s3 = ub.y;
            FFMA2(pacc[0][0], g0, s0); FFMA2(pacc[1][0], g1, s0); FFMA2(pacc[2][0], g2, s0); FFMA2(pacc[3][0], g3, s0);
            FFMA2(pacc[0][1], g0, s1); FFMA2(pacc[1][1], g1, s1); FFMA2(pacc[2][1], g2, s1); FFMA2(pacc[3][1], g3, s1);
            FFMA2(pacc[0][2], g0, s2); FFMA2(pacc[1][2], g1, s2); FFMA2(pacc[2][2], g2, s2); FFMA2(pacc[3][2], g3, s2);
            FFMA2(pacc[0][3], g0, s3); FFMA2(pacc[1][3], g1, s3); FFMA2(pacc[2][3], g2, s3); FFMA2(pacc[3][3], g3, s3);
        }
    }
    float v[4][8];
    #pragma unroll
    for (int ii = 0; ii < 4; ii++)
        #pragma unroll
        for (int rp = 0; rp < 4; rp++)
            UNPACK2(v[ii][2 * rp], v[ii][2 * rp + 1], pacc[ii][rp]);
    float* f = g_F + (size_t)c * (RB * NXDIM);
    #pragma unroll
    for (int rr = 0; rr < 8; rr++)
        *(float4*)(f + (r0 + rr) * NXDIM + i0) =
            make_float4(v[0][rr], v[1][rr], v[2][rr], v[3][rr]);
}

// ---------------- Kernel 2b: F2[cc] = A32 @ F[2cc] + F[2cc+1] ----------------
#define FPAD 132
__global__ void __launch_bounds__(256) k_f2() {
    extern __shared__ float sm[];
    float* At  = sm;                  // [j][i] 64x64
    float* FAt = sm + NXDIM * NXDIM;  // [j][r] 64x132 (padded)
    int t = threadIdx.x, cc = blockIdx.x;
    int r0 = (t & 15) * 8, i0 = (t >> 4) * 4;

    for (int idx = t; idx < NXDIM * NXDIM; idx += 256)
        At[(idx & 63) * NXDIM + (idx >> 6)] = g_A32[idx];   // At[j][i] = A32[i][j]
    const float* fa = g_F + (size_t)(2 * cc) * (RB * NXDIM);
    for (int idx = t; idx < RB * NXDIM; idx += 256) {
        int r = idx >> 6, i = idx & 63;
        FAt[i * FPAD + r] = fa[idx];                        // FAt[j][r] = F[2cc][r][j]
    }
    __syncthreads();

    float acc[4][8];
    #pragma unroll
    for (int ii = 0; ii < 4; ii++)
        #pragma unroll
        for (int rr = 0; rr < 8; rr++) acc[ii][rr] = 0.f;

    #pragma unroll 8
    for (int j = 0; j < NXDIM; j++) {
        float4 a  = *(const float4*)(At + j * NXDIM + i0);
        float4 pa = *(const float4*)(FAt + j * FPAD + r0);
        float4 pb = *(const float4*)(FAt + j * FPAD + r0 + 4);
        float av[4] = {a.x, a.y, a.z, a.w};
        float sv[8] = {pa.x, pa.y, pa.z, pa.w, pb.x, pb.y, pb.z, pb.w};
        #pragma unroll
        for (int ii = 0; ii < 4; ii++)
            #pragma unroll
            for (int rr = 0; rr < 8; rr++)
                acc[ii][rr] += av[ii] * sv[rr];
    }

    const float* fb = g_F + (size_t)(2 * cc + 1) * (RB * NXDIM);
    float* f2 = g_F2 + (size_t)cc * (RB * NXDIM);
    #pragma unroll
    for (int rr = 0; rr < 8; rr++) {
        float4 add = *(const float4*)(fb + (r0 + rr) * NXDIM + i0);
        *(float4*)(f2 + (r0 + rr) * NXDIM + i0) =
            make_float4(acc[0][rr] + add.x, acc[1][rr] + add.y,
                        acc[2][rr] + add.z, acc[3][rr] + add.w);
    }
}

// ---------------- Kernel 3: 2-way block scan (A32 & A64 paths) ----------------
// Per iteration cc (128 iters): Xs[2cc]=x ; Xs[2cc+1]=A32 x + F[2cc] ;
// x = A64 x + F2[cc].  Two independent matvecs per barrier.
__global__ void __launch_bounds__(128) k_scan() {
    __shared__ float xsh[2][NXDIM];
    int r = blockIdx.x;
    int t = threadIdx.x;
    int i = t >> 1, h = t & 1;

    float a32[32], a64[32];
    #pragma unroll
    for (int jj = 0; jj < 32; jj += 4) {
        float4 v = *(const float4*)(g_A32 + i * NXDIM + h * 32 + jj);
        a32[jj] = v.x; a32[jj + 1] = v.y; a32[jj + 2] = v.z; a32[jj + 3] = v.w;
        float4 w = *(const float4*)(g_A64 + i * NXDIM + h * 32 + jj);
        a64[jj] = w.x; a64[jj + 1] = w.y; a64[jj + 2] = w.z; a64[jj + 3] = w.w;
    }

    const int PF = 4;
    float fbuf[PF], f2buf[PF];
    #pragma unroll
    for (int p = 0; p < PF; p++) {
        fbuf[p]  = g_F [((size_t)(2 * p) * RB + r) * NXDIM + i];
        f2buf[p] = g_F2[((size_t)p       * RB + r) * NXDIM + i];
    }

    float x = 0.f;
    if (t < NXDIM) xsh[0][t] = 0.f;
    __syncthreads();
    int cur = 0;
    for (int cc = 0; cc < MBLK2; cc++) {
        size_t c = 2 * (size_t)cc;
        if (h) g_Xs[(c * RB + r) * NXDIM + i] = x;
        float fv  = fbuf [cc & (PF - 1)];
        float f2v = f2buf[cc & (PF - 1)];
        if (cc + PF < MBLK2) {
            fbuf [cc & (PF - 1)] = g_F [((size_t)(2 * (cc + PF)) * RB + r) * NXDIM + i];
            f2buf[cc & (PF - 1)] = g_F2[((size_t)(cc + PF)       * RB + r) * NXDIM + i];
        }
        float p0 = 0.f, p1 = 0.f, p2 = 0.f, p3 = 0.f;
        float q0 = 0.f, q1 = 0.f, q2 = 0.f, q3 = 0.f;
        const float* xh = &xsh[cur][h * 32];
        #pragma unroll
        for (int jj = 0; jj < 32; jj += 4) {
            float4 xv = *(const float4*)(xh + jj);
            p0 += a32[jj]     * xv.x;  q0 += a64[jj]     * xv.x;
            p1 += a32[jj + 1] * xv.y;  q1 += a64[jj + 1] * xv.y;
            p2 += a32[jj + 2] * xv.z;  q2 += a64[jj + 2] * xv.z;
            p3 += a32[jj + 3] * xv.w;  q3 += a64[jj + 3] * xv.w;
        }
        float part1 = (p0 + p1) + (p2 + p3);
        float part2 = (q0 + q1) + (q2 + q3);
        part1 += __shfl_xor_sync(0xffffffffu, part1, 1);
        part2 += __shfl_xor_sync(0xffffffffu, part2, 1);
        float y1 = part1 + fv;
        if (h) g_Xs[((c + 1) * RB + r) * NXDIM + i] = y1;
        x = part2 + f2v;
        if (!h) xsh[cur ^ 1][i] = x;
        __syncthreads();
        cur ^= 1;
    }
}

// ---------------- Kernel 4: expansion (R8 verbatim) ----------------
#define SSLOT (NXDIM * RB)
#define USLOT (NUDIM * RB)
__global__ void __launch_bounds__(256, 2) k_expand(
    const float* __restrict__ u, const float* __restrict__ A,
    const float* __restrict__ Bu, const float* __restrict__ Cy,
    const float* __restrict__ Dyu,
    float* __restrict__ outY, float* __restrict__ outX) {
    extern __shared__ float sm[];
    float* At  = sm;
    float* Bt  = At + NXDIM * NXDIM;
    float* CsT = Bt + NUDIM * NXDIM;
    float* ssh = CsT + NXDIM * NYDIM;        // 2 x 8192
    float* ush = ssh + 2 * SSLOT;            // 2 x 512

    int t = threadIdx.x, c = blockIdx.x;
    int w = t >> 5, l = t & 31;
    int iW = (w & 1) << 5, rW = (w >> 1) << 5;
    int i0 = iW + ((l & 7) << 2);
    int r0 = rW + ((l >> 3) << 3);

    for (int idx = t; idx < NXDIM * NXDIM; idx += 256)
        At[(idx % NXDIM) * NXDIM + (idx / NXDIM)] = A[idx];
    if (t < NUDIM * NXDIM) Bt[(t & 3) * NXDIM + (t >> 2)] = Bu[t];
    if (t < NXDIM * NYDIM) CsT[t] = Cy[(t & 3) * NXDIM + (t >> 2)];

    float d00 = Dyu[0],  d01 = Dyu[1],  d02 = Dyu[2],  d03 = Dyu[3];
    float d10 = Dyu[4],  d11 = Dyu[5],  d12 = Dyu[6],  d13 = Dyu[7];
    float d20 = Dyu[8],  d21 = Dyu[9],  d22 = Dyu[10], d23 = Dyu[11];
    float d30 = Dyu[12], d31 = Dyu[13], d32 = Dyu[14], d33 = Dyu[15];

    ull pacc[4][4];
    {
        const float* xs = g_Xs + (size_t)c * (RB * NXDIM);
        float vv[8][4];
        #pragma unroll
        for (int rr = 0; rr < 8; rr++) {
            float4 v = *(const float4*)(xs + (r0 + rr) * NXDIM + i0);
            vv[rr][0] = v.x; vv[rr][1] = v.y; vv[rr][2] = v.z; vv[rr][3] = v.w;
        }
        #pragma unroll
        for (int ii = 0; ii < 4; ii++)
            #pragma unroll
            for (int rp = 0; rp < 4; rp++)
                PACK2(pacc[ii][rp], vv[2 * rp][ii], vv[2 * rp + 1][ii]);
    }
    #pragma unroll
    for (int ii = 0; ii < 4; ii++) {
        int i = i0 + ii;
        int rs = swz(i, r0);
        *(ulonglong2*)(ssh + i * RB + rs)       = make_ulonglong2(pacc[ii][0], pacc[ii][1]);
        *(ulonglong2*)(ssh + i * RB + (rs ^ 4)) = make_ulonglong2(pacc[ii][2], pacc[ii][3]);
    }

    const float* ub = u + (size_t)c * LBLK * (NUDIM * RB);
    ((float2*)ush)[t] = *(const float2*)(ub + t * 2);
    float2 upf = *(const float2*)(ub + 1 * (NUDIM * RB) + t * 2);
    int yr = t & 127;
    __syncthreads();

    for (int d = 0; d < LBLK; d++) {
        float* sshC = ssh + (d & 1) * SSLOT;
        float* sshN = ssh + ((d & 1) ^ 1) * SSLOT;
        float* ushC = ush + (d & 1) * USLOT;
        float* ushN = ush + ((d & 1) ^ 1) * USLOT;

        if (d + 1 < LBLK) {
            ((float2*)ushN)[t] = upf;
            if (d + 2 < LBLK)
                upf = *(const float2*)(ub + (d + 2) * (NUDIM * RB) + t * 2);
        }

        size_t k = (size_t)c * LBLK + d;

        float* xo = outX + k * (NXDIM * RB);
        #pragma unroll
        for (int ii = 0; ii < 4; ii++) {
            *(ulonglong2*)(xo + (size_t)(i0 + ii) * RB + r0)     = make_ulonglong2(pacc[ii][0], pacc[ii][1]);
            *(ulonglong2*)(xo + (size_t)(i0 + ii) * RB + r0 + 4) = make_ulonglong2(pacc[ii][2], pacc[ii][3]);
        }

        if (t < 128) {
            float u0 = ushC[yr], u1 = ushC[RB + yr], u2 = ushC[2 * RB + yr], u3 = ushC[3 * RB + yr];
            float y0 = d00 * u0 + d01 * u1 + d02 * u2 + d03 * u3;
            float y1 = d10 * u0 + d11 * u1 + d12 * u2 + d13 * u3;
            float y2 = d20 * u0 + d21 * u1 + d22 * u2 + d23 * u3;
            float y3 = d30 * u0 + d31 * u1 + d32 * u2 + d33 * u3;
            #pragma unroll 8
            for (int j = 0; j < NXDIM; j++) {
                float s = sshC[j * RB + (yr ^ (((j >> 2) & 7) << 2))];
                float4 cv = *(const float4*)(CsT + j * 4);
                y0 += cv.x * s; y1 += cv.y * s; y2 += cv.z * s; y3 += cv.w * s;
            }
            float* yo = outY + k * (NYDIM * RB);
            yo[yr] = y0; yo[RB + yr] = y1; yo[2 * RB + yr] = y2; yo[3 * RB + yr] = y3;
        }

        #pragma unroll
        for (int ii = 0; ii < 4; ii++)
            #pragma unroll
            for (int rp = 0; rp < 4; rp++) pacc[ii][rp] = 0ull;

        #pragma unroll
        for (int q = 0; q < NUDIM; q++) {
            float4 b = *(const float4*)(Bt + q * NXDIM + i0);
            ull b0, b1, b2, b3;
            PACKB(b0, b.x); PACKB(b1, b.y); PACKB(b2, b.z); PACKB(b3, b.w);
            ulonglong2 ua = *(const ulonglong2*)(ushC + q * RB + r0);
            ulonglong2 ubp = *(const ulonglong2*)(ushC + q * RB + r0 + 4);
            ull s0 = ua.x, s1 = ua.y, s2 = ubp.x, s3 = ubp.y;
            FFMA2(pacc[0][0], b0, s0); FFMA2(pacc[1][0], b1, s0); FFMA2(pacc[2][0], b2, s0); FFMA2(pacc[3][0], b3, s0);
            FFMA2(pacc[0][1], b0, s1); FFMA2(pacc[1][1], b1, s1); FFMA2(pacc[2][1], b2, s1); FFMA2(pacc[3][1], b3, s1);
            FFMA2(pacc[0][2], b0, s2); FFMA2(pacc[1][2], b1, s2); FFMA2(pacc[2][2], b2, s2); FFMA2(pacc[3][2], b3, s2);
            FFMA2(pacc[0][3], b0, s3); FFMA2(pacc[1][3], b1, s3); FFMA2(pacc[2][3], b2, s3); FFMA2(pacc[3][3], b3, s3);
        }
        #pragma unroll 8
        for (int j = 0; j < NXDIM; j++) {
            float4 a = *(const float4*)(At + j * NXDIM + i0);
            ull a0, a1, a2, a3;
            PACKB(a0, a.x); PACKB(a1, a.y); PACKB(a2, a.z); PACKB(a3, a.w);
            int rs = j * RB + swz(j, r0);
            ulonglong2 sa = *(const ulonglong2*)(sshC + rs);
            ulonglong2 sb = *(const ulonglong2*)(sshC + (rs ^ 4));
            ull s0 = sa.x, s1 = sa.y, s2 = sb.x, s3 = sb.y;
            FFMA2(pacc[0][0], a0, s0); FFMA2(pacc[1][0], a1, s0); FFMA2(pacc[2][0], a2, s0); FFMA2(pacc[3][0], a3, s0);
            FFMA2(pacc[0][1], a0, s1); FFMA2(pacc[1][1], a1, s1); FFMA2(pacc[2][1], a2, s1); FFMA2(pacc[3][1], a3, s1);
            FFMA2(pacc[0][2], a0, s2); FFMA2(pacc[1][2], a1, s2); FFMA2(pacc[2][2], a2, s2); FFMA2(pacc[3][2], a3, s2);
            FFMA2(pacc[0][3], a0, s3); FFMA2(pacc[1][3], a1, s3); FFMA2(pacc[2][3], a2, s3); FFMA2(pacc[3][3], a3, s3);
        }

        #pragma unroll
        for (int ii = 0; ii < 4; ii++) {
            int i = i0 + ii;
            int rs = swz(i, r0);
            *(ulonglong2*)(sshN + i * RB + rs)       = make_ulonglong2(pacc[ii][0], pacc[ii][1]);
            *(ulonglong2*)(sshN + i * RB + (rs ^ 4)) = make_ulonglong2(pacc[ii][2], pacc[ii][3]);
        }
        __syncthreads();
    }
}

// ---------------------------------------------------------------------------
extern "C" void kernel_launch(void* const* d_in, const int* in_sizes, int n_in,
                              void* d_out, int out_size) {
    (void)in_sizes; (void)n_in; (void)out_size;
    const float* u   = (const float*)d_in[0];
    const float* A   = (const float*)d_in[1];
    const float* Bu  = (const float*)d_in[2];
    const float* Cy  = (const float*)d_in[3];
    const float* Dyu = (const float*)d_in[4];
    float* outY = (float*)d_out;
    float* outX = outY + (size_t)NSTEP * NYDIM * RB;

    const int smem_powers = (NXDIM * 65 + NXDIM * 128) * (int)sizeof(float);
    const int smem_fgemm  = (128 * NXDIM + 32 * 128) * (int)sizeof(float);
    const int smem_f2     = (NXDIM * NXDIM + NXDIM * FPAD) * (int)sizeof(float);  // ~49 KB
    const int smem_expand = (NXDIM * NXDIM + NUDIM * NXDIM + NXDIM * NYDIM +
                             2 * SSLOT + 2 * USLOT) * (int)sizeof(float);         // ~88 KB

    cudaFuncSetAttribute(k_powers, cudaFuncAttributeMaxDynamicSharedMemorySize, smem_powers);
    cudaFuncSetAttribute(k_fgemm,  cudaFuncAttributeMaxDynamicSharedMemorySize, smem_fgemm);
    cudaFuncSetAttribute(k_f2,     cudaFuncAttributeMaxDynamicSharedMemorySize, smem_f2);
    cudaFuncSetAttribute(k_expand, cudaFuncAttributeMaxDynamicSharedMemorySize, smem_expand);

    k_powers<<<1, 1024, smem_powers>>>(A, Bu);
    k_fgemm<<<MBLK, 256, smem_fgemm>>>(u);
    k_f2<<<MBLK2, 256, smem_f2>>>();
    k_scan<<<RB, 128>>>();
    k_expand<<<MBLK, 256, smem_expand>>>(u, A, Bu, Cy, Dyu, outY, outX);
}

// round 17
// speedup vs baseline: 1.0080x; 1.0080x over previous
#include <cuda_runtime.h>

#define NSTEP 8192
#define NUDIM 4
#define RB    128
#define NXDIM 64
#define NYDIM 4
#define LBLK  32
#define MBLK  (NSTEP / LBLK)
#define NSUP  16
#define SUBB  (MBLK / NSUP)      // 16 blocks per superblock

__device__ float g_F   [MBLK * RB * NXDIM];
__device__ float g_Xs  [MBLK * RB * NXDIM];
__device__ float g_SF  [NSUP * RB * NXDIM];
__device__ float g_xsup[NSUP * RB * NXDIM];
__device__ float g_A32 [NXDIM * NXDIM];
__device__ float g_A512[NXDIM * NXDIM];
__device__ float g_G   [NXDIM * (LBLK * NUDIM)];

typedef unsigned long long ull;
#define FFMA2(d, a, b)  asm("fma.rn.f32x2 %0, %1, %2, %0;" : "+l"(d) : "l"(a), "l"(b))
#define PACKB(d, s)     asm("mov.b64 %0, {%1, %1};" : "=l"(d) : "f"(s))
#define PACK2(d, lo, hi) asm("mov.b64 %0, {%1, %2};" : "=l"(d) : "f"(lo), "f"(hi))
#define UNPACK2(lo, hi, p) asm("mov.b64 {%0, %1}, %2;" : "=f"(lo), "=f"(hi) : "l"(p))

__device__ __forceinline__ int swz(int row, int r) { return r ^ (((row >> 2) & 7) << 2); }

// ---------------- Kernel 1: A^32, A^512 + G by doubling, 1024 threads ----------------
__global__ void __launch_bounds__(1024) k_powers(const float* __restrict__ A, const float* __restrict__ Bu) {
    extern __shared__ float ps[];
    float* Asm = ps;                 // 64 x 65
    float* P   = ps + NXDIM * 65;    // 64 x 128
    int t = threadIdx.x;

    for (int idx = t; idx < NXDIM * NXDIM; idx += 1024)
        Asm[(idx >> 6) * 65 + (idx & 63)] = A[idx];
    if (t < 256) P[(t >> 2) * 128 + (t & 3)] = Bu[t];
    __syncthreads();

    int W = 4;
    int oi = t >> 4, oj0 = (t & 15) * 4;
    for (int s = 0; s < 5; s++) {
        for (int idx = t; idx < NXDIM * W; idx += 1024) {
            int i = idx / W, k = idx % W;
            float s0 = 0.f, s1 = 0.f, s2 = 0.f, s3 = 0.f;
            #pragma unroll 4
            for (int j = 0; j < NXDIM; j += 4) {
                s0 += Asm[i * 65 + j]     * P[(j)     * 128 + k];
                s1 += Asm[i * 65 + j + 1] * P[(j + 1) * 128 + k];
                s2 += Asm[i * 65 + j + 2] * P[(j + 2) * 128 + k];
                s3 += Asm[i * 65 + j + 3] * P[(j + 3) * 128 + k];
            }
            P[i * 128 + W + k] = (s0 + s1) + (s2 + s3);
        }
        __syncthreads();
        float a0 = 0.f, a1 = 0.f, a2 = 0.f, a3 = 0.f;
        #pragma unroll 8
        for (int k = 0; k < NXDIM; k++) {
            float a = Asm[oi * 65 + k];
            const float* row = Asm + k * 65 + oj0;
            a0 += a * row[0]; a1 += a * row[1]; a2 += a * row[2]; a3 += a * row[3];
        }
        __syncthreads();
        Asm[oi * 65 + oj0]     = a0;
        Asm[oi * 65 + oj0 + 1] = a1;
        Asm[oi * 65 + oj0 + 2] = a2;
        Asm[oi * 65 + oj0 + 3] = a3;
        __syncthreads();
        W <<= 1;
    }

    // Asm = A^32
    for (int idx = t; idx < NXDIM * NXDIM; idx += 1024)
        g_A32[idx] = Asm[(idx >> 6) * 65 + (idx & 63)];
    for (int idx = t; idx < NXDIM * 128; idx += 1024) {
        int i = idx >> 7, col = idx & 127;
        int m = col >> 2, q = col & 3;
        g_G[i * 128 + ((31 - m) << 2) + q] = P[idx];
    }
    __syncthreads();

    // 4 more squarings: A^32 -> A^64 -> A^128 -> A^256 -> A^512
    for (int e = 0; e < 4; e++) {
        float a0 = 0.f, a1 = 0.f, a2 = 0.f, a3 = 0.f;
        #pragma unroll 8
        for (int k = 0; k < NXDIM; k++) {
            float a = Asm[oi * 65 + k];
            const float* row = Asm + k * 65 + oj0;
            a0 += a * row[0]; a1 += a * row[1]; a2 += a * row[2]; a3 += a * row[3];
        }
        __syncthreads();
        Asm[oi * 65 + oj0]     = a0;
        Asm[oi * 65 + oj0 + 1] = a1;
        Asm[oi * 65 + oj0 + 2] = a2;
        Asm[oi * 65 + oj0 + 3] = a3;
        __syncthreads();
    }
    for (int idx = t; idx < NXDIM * NXDIM; idx += 1024)
        g_A512[idx] = Asm[(idx >> 6) * 65 + (idx & 63)];
}

// ---------------- Kernel 2: f_c = G @ U_c (FFMA2, unchanged) ----------------
__global__ void __launch_bounds__(256) k_fgemm(const float* __restrict__ u) {
    extern __shared__ float sm[];
    float* Gt = sm;
    float* Ut = sm + 128 * NXDIM;
    int t = threadIdx.x, c = blockIdx.x;
    int rb = t & 15, ib = t >> 4;
    int r0 = rb * 8, i0 = ib * 4;
    for (int idx = t; idx < 128 * NXDIM; idx += 256) {
        int i = idx >> 7, k = idx & 127;
        Gt[k * NXDIM + i] = g_G[idx];
    }
    ull pacc[4][4];
    #pragma unroll
    for (int ii = 0; ii < 4; ii++)
        #pragma unroll
        for (int rp = 0; rp < 4; rp++) pacc[ii][rp] = 0ull;
    const float* ublk = u + (size_t)c * (LBLK * NUDIM * RB);
    for (int k0 = 0; k0 < 128; k0 += 32) {
        __syncthreads();
        for (int idx = t; idx < 32 * 128; idx += 256)
            Ut[idx] = ublk[(k0 + (idx >> 7)) * 128 + (idx & 127)];
        __syncthreads();
        #pragma unroll 8
        for (int kk = 0; kk < 32; kk++) {
            float4 g = *(const float4*)(Gt + (k0 + kk) * NXDIM + i0);
            ull g0, g1, g2, g3;
            PACKB(g0, g.x); PACKB(g1, g.y); PACKB(g2, g.z); PACKB(g3, g.w);
            ulonglong2 ua = *(const ulonglong2*)(Ut + kk * 128 + r0);
            ulonglong2 ub = *(const ulonglong2*)(Ut + kk * 128 + r0 + 4);
            ull s0 = ua.x, s1 = ua.y, s2 = ub.x, s3 = ub.y;
            FFMA2(pacc[0][0], g0, s0); FFMA2(pacc[1][0], g1, s0); FFMA2(pacc[2][0], g2, s0); FFMA2(pacc[3][0], g3, s0);
            FFMA2(pacc[0][1], g0, s1); FFMA2(pacc[1][1], g1, s1); FFMA2(pacc[2][1], g2, s1); FFMA2(pacc[3][1], g3, s1);
            FFMA2(pacc[0][2], g0, s2); FFMA2(pacc[1][2], g1, s2); FFMA2(pacc[2][2], g2, s2); FFMA2(pacc[3][2], g3, s2);
            FFMA2(pacc[0][3], g0, s3); FFMA2(pacc[1][3], g1, s3); FFMA2(pacc[2][3], g2, s3); FFMA2(pacc[3][3], g3, s3);
        }
    }
    float v[4][8];
    #pragma unroll
    for (int ii = 0; ii < 4; ii++)
        #pragma unroll
        for (int rp = 0; rp < 4; rp++)
            UNPACK2(v[ii][2 * rp], v[ii][2 * rp + 1], pacc[ii][rp]);
    float* f = g_F + (size_t)c * (RB * NXDIM);
    #pragma unroll
    for (int rr = 0; rr < 8; rr++)
        *(float4*)(f + (r0 + rr) * NXDIM + i0) =
            make_float4(v[0][rr], v[1][rr], v[2][rr], v[3][rr]);
}

// ---------------- Shared scan matvec helper ----------------
__device__ __forceinline__ float scan_step(const float* arow, const float* xh) {
    float v0 = 0.f, v1 = 0.f, v2 = 0.f, v3 = 0.f;
    #pragma unroll
    for (int jj = 0; jj < 32; jj += 4) {
        float4 xv = *(const float4*)(xh + jj);
        v0 += arow[jj]     * xv.x;
        v1 += arow[jj + 1] * xv.y;
        v2 += arow[jj + 2] * xv.z;
        v3 += arow[jj + 3] * xv.w;
    }
    float part = (v0 + v1) + (v2 + v3);
    part += __shfl_xor_sync(0xffffffffu, part, 1);
    return part;
}

// ---------------- Kernel 3a: per-superblock carry (zero init, depth 16) ----------------
__global__ void __launch_bounds__(128) k_carry() {
    __shared__ float xsh[2][NXDIM];
    int S = blockIdx.x >> 7, r = blockIdx.x & 127;
    int t = threadIdx.x, i = t >> 1, h = t & 1;
    float arow[32];
    #pragma unroll
    for (int jj = 0; jj < 32; jj += 4) {
        float4 v = *(const float4*)(g_A32 + i * NXDIM + h * 32 + jj);
        arow[jj] = v.x; arow[jj + 1] = v.y; arow[jj + 2] = v.z; arow[jj + 3] = v.w;
    }
    float x = 0.f;
    if (t < NXDIM) xsh[0][t] = 0.f;
    __syncthreads();
    int cur = 0, base = S * SUBB;
    for (int k = 0; k < SUBB; k++) {
        float fv = g_F[((size_t)(base + k) * RB + r) * NXDIM + i];
        x = scan_step(arow, &xsh[cur][h * 32]) + fv;
        if (!h) xsh[cur ^ 1][i] = x;
        __syncthreads();
        cur ^= 1;
    }
    if (h) g_SF[((size_t)S * RB + r) * NXDIM + i] = x;
}

// ---------------- Kernel 3b: superblock scan (depth 16) ----------------
__global__ void __launch_bounds__(128) k_supscan() {
    __shared__ float xsh[2][NXDIM];
    int r = blockIdx.x;
    int t = threadIdx.x, i = t >> 1, h = t & 1;
    float arow[32];
    #pragma unroll
    for (int jj = 0; jj < 32; jj += 4) {
        float4 v = *(const float4*)(g_A512 + i * NXDIM + h * 32 + jj);
        arow[jj] = v.x; arow[jj + 1] = v.y; arow[jj + 2] = v.z; arow[jj + 3] = v.w;
    }
    float x = 0.f;
    if (t < NXDIM) xsh[0][t] = 0.f;
    __syncthreads();
    int cur = 0;
    for (int S = 0; S < NSUP; S++) {
        if (h) g_xsup[((size_t)S * RB + r) * NXDIM + i] = x;
        float fv = g_SF[((size_t)S * RB + r) * NXDIM + i];
        x = scan_step(arow, &xsh[cur][h * 32]) + fv;
        if (!h) xsh[cur ^ 1][i] = x;
        __syncthreads();
        cur ^= 1;
    }
}

// ---------------- Kernel 3c: final per-superblock scan from true init (depth 16) ----------------
__global__ void __launch_bounds__(128) k_finscan() {
    __shared__ float xsh[2][NXDIM];
    int S = blockIdx.x >> 7, r = blockIdx.x & 127;
    int t = threadIdx.x, i = t >> 1, h = t & 1;
    float arow[32];
    #pragma unroll
    for (int jj = 0; jj < 32; jj += 4) {
        float4 v = *(const float4*)(g_A32 + i * NXDIM + h * 32 + jj);
        arow[jj] = v.x; arow[jj + 1] = v.y; arow[jj + 2] = v.z; arow[jj + 3] = v.w;
    }
    float x = g_xsup[((size_t)S * RB + r) * NXDIM + i];
    if (!h) xsh[0][i] = x;
    __syncthreads();
    int cur = 0, base = S * SUBB;
    for (int k = 0; k < SUBB; k++) {
        if (h) g_Xs[((size_t)(base + k) * RB + r) * NXDIM + i] = x;
        float fv = g_F[((size_t)(base + k) * RB + r) * NXDIM + i];
        x = scan_step(arow, &xsh[cur][h * 32]) + fv;
        if (!h) xsh[cur ^ 1][i] = x;
        __syncthreads();
        cur ^= 1;
    }
}

// ---------------- Kernel 4: expansion (R8 verbatim) ----------------
#define SSLOT (NXDIM * RB)
#define USLOT (NUDIM * RB)
__global__ void __launch_bounds__(256, 2) k_expand(
    const float* __restrict__ u, const float* __restrict__ A,
    const float* __restrict__ Bu, const float* __restrict__ Cy,
    const float* __restrict__ Dyu,
    float* __restrict__ outY, float* __restrict__ outX) {
    extern __shared__ float sm[];
    float* At  = sm;
    float* Bt  = At + NXDIM * NXDIM;
    float* CsT = Bt + NUDIM * NXDIM;
    float* ssh = CsT + NXDIM * NYDIM;        // 2 x 8192
    float* ush = ssh + 2 * SSLOT;            // 2 x 512

    int t = threadIdx.x, c = blockIdx.x;
    int w = t >> 5, l = t & 31;
    int iW = (w & 1) << 5, rW = (w >> 1) << 5;
    int i0 = iW + ((l & 7) << 2);
    int r0 = rW + ((l >> 3) << 3);

    for (int idx = t; idx < NXDIM * NXDIM; idx += 256)
        At[(idx % NXDIM) * NXDIM + (idx / NXDIM)] = A[idx];
    if (t < NUDIM * NXDIM) Bt[(t & 3) * NXDIM + (t >> 2)] = Bu[t];
    if (t < NXDIM * NYDIM) CsT[t] = Cy[(t & 3) * NXDIM + (t >> 2)];

    float d00 = Dyu[0],  d01 = Dyu[1],  d02 = Dyu[2],  d03 = Dyu[3];
    float d10 = Dyu[4],  d11 = Dyu[5],  d12 = Dyu[6],  d13 = Dyu[7];
    float d20 = Dyu[8],  d21 = Dyu[9],  d22 = Dyu[10], d23 = Dyu[11];
    float d30 = Dyu[12], d31 = Dyu[13], d32 = Dyu[14], d33 = Dyu[15];

    ull pacc[4][4];
    {
        const float* xs = g_Xs + (size_t)c * (RB * NXDIM);
        float vv[8][4];
        #pragma unroll
        for (int rr = 0; rr < 8; rr++) {
            float4 v = *(const float4*)(xs + (r0 + rr) * NXDIM + i0);
            vv[rr][0] = v.x; vv[rr][1] = v.y; vv[rr][2] = v.z; vv[rr][3] = v.w;
        }
        #pragma unroll
        for (int ii = 0; ii < 4; ii++)
            #pragma unroll
            for (int rp = 0; rp < 4; rp++)
                PACK2(pacc[ii][rp], vv[2 * rp][ii], vv[2 * rp + 1][ii]);
    }
    #pragma unroll
    for (int ii = 0; ii < 4; ii++) {
        int i = i0 + ii;
        int rs = swz(i, r0);
        *(ulonglong2*)(ssh + i * RB + rs)       = make_ulonglong2(pacc[ii][0], pacc[ii][1]);
        *(ulonglong2*)(ssh + i * RB + (rs ^ 4)) = make_ulonglong2(pacc[ii][2], pacc[ii][3]);
    }

    const float* ub = u + (size_t)c * LBLK * (NUDIM * RB);
    ((float2*)ush)[t] = *(const float2*)(ub + t * 2);
    float2 upf = *(const float2*)(ub + 1 * (NUDIM * RB) + t * 2);
    int yr = t & 127;
    __syncthreads();

    for (int d = 0; d < LBLK; d++) {
        float* sshC = ssh + (d & 1) * SSLOT;
        float* sshN = ssh + ((d & 1) ^ 1) * SSLOT;
        float* ushC = ush + (d & 1) * USLOT;
        float* ushN = ush + ((d & 1) ^ 1) * USLOT;

        if (d + 1 < LBLK) {
            ((float2*)ushN)[t] = upf;
            if (d + 2 < LBLK)
                upf = *(const float2*)(ub + (d + 2) * (NUDIM * RB) + t * 2);
        }

        size_t k = (size_t)c * LBLK + d;

        float* xo = outX + k * (NXDIM * RB);
        #pragma unroll
        for (int ii = 0; ii < 4; ii++) {
            *(ulonglong2*)(xo + (size_t)(i0 + ii) * RB + r0)     = make_ulonglong2(pacc[ii][0], pacc[ii][1]);
            *(ulonglong2*)(xo + (size_t)(i0 + ii) * RB + r0 + 4) = make_ulonglong2(pacc[ii][2], pacc[ii][3]);
        }

        if (t < 128) {
            float u0 = ushC[yr], u1 = ushC[RB + yr], u2 = ushC[2 * RB + yr], u3 = ushC[3 * RB + yr];
            float y0 = d00 * u0 + d01 * u1 + d02 * u2 + d03 * u3;
            float y1 = d10 * u0 + d11 * u1 + d12 * u2 + d13 * u3;
            float y2 = d20 * u0 + d21 * u1 + d22 * u2 + d23 * u3;
            float y3 = d30 * u0 + d31 * u1 + d32 * u2 + d33 * u3;
            #pragma unroll 8
            for (int j = 0; j < NXDIM; j++) {
                float s = sshC[j * RB + (yr ^ (((j >> 2) & 7) << 2))];
                float4 cv = *(const float4*)(CsT + j * 4);
                y0 += cv.x * s; y1 += cv.y * s; y2 += cv.z * s; y3 += cv.w * s;
            }
            float* yo = outY + k * (NYDIM * RB);
            yo[yr] = y0; yo[RB + yr] = y1; yo[2 * RB + yr] = y2; yo[3 * RB + yr] = y3;
        }

        #pragma unroll
        for (int ii = 0; ii < 4; ii++)
            #pragma unroll
            for (int rp = 0; rp < 4; rp++) pacc[ii][rp] = 0ull;

        #pragma unroll
        for (int q = 0; q < NUDIM; q++) {
            float4 b = *(const float4*)(Bt + q * NXDIM + i0);
            ull b0, b1, b2, b3;
            PACKB(b0, b.x); PACKB(b1, b.y); PACKB(b2, b.z); PACKB(b3, b.w);
            ulonglong2 ua = *(const ulonglong2*)(ushC + q * RB + r0);
            ulonglong2 ubp = *(const ulonglong2*)(ushC + q * RB + r0 + 4);
            ull s0 = ua.x, s1 = ua.y, s2 = ubp.x, s3 = ubp.y;
            FFMA2(pacc[0][0], b0, s0); FFMA2(pacc[1][0], b1, s0); FFMA2(pacc[2][0], b2, s0); FFMA2(pacc[3][0], b3, s0);
            FFMA2(pacc[0][1], b0, s1); FFMA2(pacc[1][1], b1, s1); FFMA2(pacc[2][1], b2, s1); FFMA2(pacc[3][1], b3, s1);
            FFMA2(pacc[0][2], b0, s2); FFMA2(pacc[1][2], b1, s2); FFMA2(pacc[2][2], b2, s2); FFMA2(pacc[3][2], b3, s2);
            FFMA2(pacc[0][3], b0, s3); FFMA2(pacc[1][3], b1, s3); FFMA2(pacc[2][3], b2, s3); FFMA2(pacc[3][3], b3, s3);
        }
        #pragma unroll 8
        for (int j = 0; j < NXDIM; j++) {
            float4 a = *(const float4*)(At + j * NXDIM + i0);
            ull a0, a1, a2, a3;
            PACKB(a0, a.x); PACKB(a1, a.y); PACKB(a2, a.z); PACKB(a3, a.w);
            int rs = j * RB + swz(j, r0);
            ulonglong2 sa = *(const ulonglong2*)(sshC + rs);
            ulonglong2 sb = *(const ulonglong2*)(sshC + (rs ^ 4));
            ull s0 = sa.x, s1 = sa.y, s2 = sb.x, s3 = sb.y;
            FFMA2(pacc[0][0], a0, s0); FFMA2(pacc[1][0], a1, s0); FFMA2(pacc[2][0], a2, s0); FFMA2(pacc[3][0], a3, s0);
            FFMA2(pacc[0][1], a0, s1); FFMA2(pacc[1][1], a1, s1); FFMA2(pacc[2][1], a2, s1); FFMA2(pacc[3][1], a3, s1);
            FFMA2(pacc[0][2], a0, s2); FFMA2(pacc[1][2], a1, s2); FFMA2(pacc[2][2], a2, s2); FFMA2(pacc[3][2], a3, s2);
            FFMA2(pacc[0][3], a0, s3); FFMA2(pacc[1][3], a1, s3); FFMA2(pacc[2][3], a2, s3); FFMA2(pacc[3][3], a3, s3);
        }

        #pragma unroll
        for (int ii = 0; ii < 4; ii++) {
            int i = i0 + ii;
            int rs = swz(i, r0);
            *(ulonglong2*)(sshN + i * RB + rs)       = make_ulonglong2(pacc[ii][0], pacc[ii][1]);
            *(ulonglong2*)(sshN + i * RB + (rs ^ 4)) = make_ulonglong2(pacc[ii][2], pacc[ii][3]);
        }
        __syncthreads();
    }
}

// ---------------------------------------------------------------------------
extern "C" void kernel_launch(void* const* d_in, const int* in_sizes, int n_in,
                              void* d_out, int out_size) {
    (void)in_sizes; (void)n_in; (void)out_size;
    const float* u   = (const float*)d_in[0];
    const float* A   = (const float*)d_in[1];
    const float* Bu  = (const float*)d_in[2];
    const float* Cy  = (const float*)d_in[3];
    const float* Dyu = (const float*)d_in[4];
    float* outY = (float*)d_out;
    float* outX = outY + (size_t)NSTEP * NYDIM * RB;

    const int smem_powers = (NXDIM * 65 + NXDIM * 128) * (int)sizeof(float);
    const int smem_fgemm  = (128 * NXDIM + 32 * 128) * (int)sizeof(float);
    const int smem_expand = (NXDIM * NXDIM + NUDIM * NXDIM + NXDIM * NYDIM +
                             2 * SSLOT + 2 * USLOT) * (int)sizeof(float);   // ~88 KB

    cudaFuncSetAttribute(k_powers, cudaFuncAttributeMaxDynamicSharedMemorySize, smem_powers);
    cudaFuncSetAttribute(k_fgemm,  cudaFuncAttributeMaxDynamicSharedMemorySize, smem_fgemm);
    cudaFuncSetAttribute(k_expand, cudaFuncAttributeMaxDynamicSharedMemorySize, smem_expand);

    k_powers<<<1, 1024, smem_powers>>>(A, Bu);
    k_fgemm<<<MBLK, 256, smem_fgemm>>>(u);
    k_carry<<<NSUP * RB, 128>>>();
    k_supscan<<<RB, 128>>>();
    k_finscan<<<NSUP * RB, 128>>>();
    k_expand<<<MBLK, 256, smem_expand>>>(u, A, Bu, Cy, Dyu, outY, outX);
}